// round 16
// baseline (speedup 1.0000x reference)
#include <cuda_runtime.h>
#include <cuda_fp16.h>
#include <cstdint>
#include <cstddef>

// ---------------------------------------------------------------------------
// Problem constants
// ---------------------------------------------------------------------------
#define B_   128
#define S_   256
#define H_   1024
#define IN_  64
#define SD_  2
#define KGEMM 1088           // u(64) + h(1024); x handled as rank-2 fp32 update
#define NKB  34              // K blocks of 32
#define NKH  17              // K blocks per K-split half
#define ZW   (SD_ + H_)      // 1026
#define NG   4096

#define OUT_ZF   ((size_t)B_ * S_ * ZW)
#define OUT_CZF  (OUT_ZF + (size_t)B_ * ZW)
#define OUT_COEF (OUT_CZF + (size_t)B_ * ZW)

// Blocked layouts: rows padded to 40 fp16 (80 B) for conflict-free LDSM
#define ROWB 40
#define XBLK_BYTES  (128 * ROWB * 2)          // 10240 per K-block
#define WBLK_BYTES  (64 * ROWB * 2)           // 5120 per (ntile64, kb)
#define NSTAGE 3                               // X pipeline stages
#define W_RES_BYTES (NKH * WBLK_BYTES)         // 87040 resident W half
#define SMEM_DYN (128 + NSTAGE * XBLK_BYTES + W_RES_BYTES)   // 117,888

// ---------------------------------------------------------------------------
// Device-global scratch
// ---------------------------------------------------------------------------
__device__ __align__(128) __half g_X[(size_t)NKB * 128 * ROWB];      // fp16 X image
__device__ __align__(128) __half g_W[(size_t)64 * NKB * 64 * ROWB];  // fp16 W image
__device__ float g_gates[2][(size_t)B_ * NG];   // two K-split partials (unit-major)
__device__ float4 g_bias4[H_];
__device__ float4 g_wawx4[H_];
__device__ float4 g_wx2a[H_];
__device__ float4 g_wx2b[H_];
__device__ float g_cstate[B_ * H_];
__device__ float g_xstate[B_ * 2];
__device__ unsigned g_bar_count;                // grid barrier (self-resetting)
__device__ unsigned g_bar_gen;                  // generation (monotonic)

// ---------------------------------------------------------------------------
// Helpers
// ---------------------------------------------------------------------------
__device__ __forceinline__ float sigf(float x) { return 1.0f / (1.0f + __expf(-x)); }
__device__ __forceinline__ float tanhfast(float x) { return 2.0f / (1.0f + __expf(-2.0f * x)) - 1.0f; }

__device__ __forceinline__ void store_x(int m, int k, float v) {
    int kb = k >> 5, kk = k & 31;
    g_X[((size_t)kb * 128 + m) * ROWB + kk] = __float2half_rn(v);
}

__device__ __forceinline__ uint32_t smem_u32(const void* p) {
    uint32_t a;
    asm("{ .reg .u64 t; cvta.to.shared.u64 t, %1; cvt.u32.u64 %0, t; }" : "=r"(a) : "l"(p));
    return a;
}

#define MBINIT(a, c)  asm volatile("mbarrier.init.shared.b64 [%0], %1;" :: "r"(a), "r"(c) : "memory")
#define MBEXPECT(a,b) asm volatile("mbarrier.arrive.expect_tx.shared.b64 _, [%0], %1;" :: "r"(a), "r"(b) : "memory")
#define MBARRIVE(a)   asm volatile("mbarrier.arrive.shared.b64 _, [%0];" :: "r"(a) : "memory")

#define MBAR_WAIT(mbar, ph) do {                                             \
    uint32_t _m = (mbar); uint32_t _p = (ph); uint32_t _ok;                  \
    asm volatile("{\n\t.reg .pred p;\n\t"                                    \
        "mbarrier.try_wait.parity.acquire.cta.shared::cta.b64 p, [%1], %2;\n\t" \
        "selp.b32 %0, 1, 0, p;\n\t}" : "=r"(_ok) : "r"(_m), "r"(_p) : "memory"); \
    while (!_ok) {                                                           \
        asm volatile("{\n\t.reg .pred p;\n\t"                                \
            "mbarrier.try_wait.parity.acquire.cta.shared::cta.b64 p, [%1], %2, 0x989680;\n\t" \
            "selp.b32 %0, 1, 0, p;\n\t}" : "=r"(_ok) : "r"(_m), "r"(_p) : "memory"); \
    }                                                                        \
} while (0)

__device__ __forceinline__ void bulk_g2s(uint32_t dst, const void* src, uint32_t bytes, uint32_t mbar) {
    asm volatile("cp.async.bulk.shared::cluster.global.mbarrier::complete_tx::bytes [%0], [%1], %2, [%3];"
                 :: "r"(dst), "l"(src), "r"(bytes), "r"(mbar) : "memory");
}

#define MMA_F16(acc, a, b)                                                   \
    asm volatile("mma.sync.aligned.m16n8k16.row.col.f32.f16.f16.f32 "       \
                 "{%0,%1,%2,%3},{%4,%5,%6,%7},{%8,%9},{%0,%1,%2,%3};"        \
                 : "+f"((acc)[0]), "+f"((acc)[1]), "+f"((acc)[2]), "+f"((acc)[3]) \
                 : "r"((a)[0]), "r"((a)[1]), "r"((a)[2]), "r"((a)[3]),       \
                   "r"((b)[0]), "r"((b)[1]))

#define LDSM_X4(r0, r1, r2, r3, addr)                                        \
    asm volatile("ldmatrix.sync.aligned.m8n8.x4.shared.b16 {%0,%1,%2,%3}, [%4];" \
                 : "=r"(r0), "=r"(r1), "=r"(r2), "=r"(r3) : "r"(addr))

// Unit-major permutation: GEMM column j -> W row (j&3)*H + (j>>2)
__device__ __forceinline__ int orig_row(int j) {
    return (j & 3) * H_ + (j >> 2);
}

// ---------------------------------------------------------------------------
// prep_w: W fp32 -> blocked, unit-major, fp16 image
// ---------------------------------------------------------------------------
__global__ void prep_w(const float* __restrict__ W) {
    int nt = blockIdx.x, kb = blockIdx.y;
    size_t base = ((size_t)(nt * NKB + kb)) * 64 * ROWB;
    for (int i = threadIdx.x; i < 64 * ROWB; i += 256) {
        int nloc = i / ROWB, kk = i % ROWB;
        int j = nt * 64 + nloc;
        int n = orig_row(j);
        int k = kb * 32 + kk;
        float v = (kk < 32 && k < KGEMM) ? W[(size_t)n * (SD_ + IN_ + H_) + (k + SD_)] : 0.0f;
        g_W[base + i] = __float2half_rn(v);
    }
}

// ---------------------------------------------------------------------------
// prep_small: pack bias / Wa / Wx / W x-columns as per-unit float4
// ---------------------------------------------------------------------------
__global__ void prep_small(const float* __restrict__ W, const float* __restrict__ WUb,
                           const float* __restrict__ Wa, const float* __restrict__ Wx) {
    int u = blockIdx.x * 256 + threadIdx.x;
    if (u >= H_) return;
    const int KW = SD_ + IN_ + H_;
    g_bias4[u] = make_float4(WUb[u], WUb[H_ + u], WUb[2 * H_ + u], WUb[3 * H_ + u]);
    g_wawx4[u] = make_float4(Wa[u], Wa[H_ + u], Wx[u], Wx[H_ + u]);
    g_wx2a[u] = make_float4(W[(size_t)u * KW], W[(size_t)(H_ + u) * KW],
                            W[(size_t)(2 * H_ + u) * KW], W[(size_t)(3 * H_ + u) * KW]);
    g_wx2b[u] = make_float4(W[(size_t)u * KW + 1], W[(size_t)(H_ + u) * KW + 1],
                            W[(size_t)(2 * H_ + u) * KW + 1], W[(size_t)(3 * H_ + u) * KW + 1]);
    if (u == 0) { g_bar_count = 0; g_bar_gen = 0; }
}

// ---------------------------------------------------------------------------
// init_pack: X image for step 0 ([u_0 | h_0]), states
// ---------------------------------------------------------------------------
__global__ void init_pack(const float* __restrict__ z0, const float* __restrict__ c0,
                          const float* __restrict__ rnn_input) {
    int b = blockIdx.x;
    for (int i = threadIdx.x; i < NKB * ROWB; i += 128) {
        int kb = i / ROWB, kk = i % ROWB;
        int k = kb * 32 + kk;
        float v = 0.0f;
        if (kk < 32) {
            if (k < IN_)            v = rnn_input[((size_t)b * S_) * IN_ + k];
            else if (k < KGEMM)     v = z0[b * ZW + SD_ + (k - IN_)];
        }
        g_X[((size_t)kb * 128 + b) * ROWB + kk] = __float2half_rn(v);
    }
    for (int n = threadIdx.x; n < H_; n += 128)
        g_cstate[b * H_ + n] = c0[b * ZW + SD_ + n];
    if (threadIdx.x < 2) g_xstate[b * 2 + threadIdx.x] = z0[b * ZW + threadIdx.x];
}

// ---------------------------------------------------------------------------
// persistent_scan: all 256 steps. gates (tid<256, W resident in smem) ->
// grid barrier -> pointwise (512 threads) -> grid barrier.
// grid = 128 CTAs (nt = bid&63, ki = bid>>6), 512 threads, 1 CTA/SM.
// ---------------------------------------------------------------------------
__global__ void __launch_bounds__(512, 1)
persistent_scan(float* __restrict__ out,
                const float* __restrict__ Wab, const float* __restrict__ Wxb,
                const float* __restrict__ Amat, const float* __restrict__ tau,
                const float* __restrict__ rnn_input) {
    extern __shared__ char dsm[];
    uint32_t ub = smem_u32(dsm);
    const int bid = blockIdx.x;
    const int nt  = bid & 63;
    const int ki  = bid >> 6;
    const int kstart = ki * NKH;
    const int tid = threadIdx.x;
    const int wid = tid >> 5;
    const int lane = tid & 31;
    const int lr = lane >> 2, lc = lane & 3;
    const int mp = wid & 3;
    const int ng = (wid >> 2) & 1;

    __shared__ float sPre[12];
    __shared__ float red[16][4];

    uint32_t mb_full[NSTAGE], mb_empty[NSTAGE];
#pragma unroll
    for (int st = 0; st < NSTAGE; st++) {
        mb_full[st]  = ub + st * 8;
        mb_empty[st] = ub + 24 + st * 8;
    }
    const uint32_t mb_w    = ub + 48;
    const uint32_t xstage  = ub + 128;
    const uint32_t wres    = xstage + NSTAGE * XBLK_BYTES;

    // ldmatrix per-lane byte offsets
    const int a_row = mp * 32 + (lane & 7) + ((lane >> 3) & 1) * 8;
    const uint32_t a_off0 = (uint32_t)(a_row * 80 + (lane >> 4) * 16);
    const uint32_t a_off1 = a_off0 + 16 * 80;
    const int b_row0 = ng * 32 + (lane >> 4) * 8 + (lane & 7);
    const uint32_t b_off0 = (uint32_t)(b_row0 * 80 + ((lane >> 3) & 1) * 16);
    const uint32_t b_off1 = b_off0 + 16 * 80;

    if (tid == 0) {
#pragma unroll
        for (int st = 0; st < NSTAGE; st++) {
            MBINIT(mb_full[st], 1);
            MBINIT(mb_empty[st], 256);
        }
        MBINIT(mb_w, 1);
        asm volatile("fence.proxy.async.shared::cta;" ::: "memory");
    }
    __syncthreads();

    // ---- Load resident W half once (17 blocks x 5120 B) ----
    if (tid == 0) {
        MBEXPECT(mb_w, W_RES_BYTES);
#pragma unroll
        for (int kb = 0; kb < NKH; kb++) {
            size_t woff = (size_t)(nt * NKB + kstart + kb) * WBLK_BYTES;
            bulk_g2s(wres + kb * WBLK_BYTES, (const char*)g_W + woff, WBLK_BYTES, mb_w);
        }
    }
    if (tid < 256) { MBAR_WAIT(mb_w, 0); }

    // Persistent pipeline state
    int fph[NSTAGE] = {0, 0, 0};      // consumer phase per stage (gates threads)
    int eph[NSTAGE] = {0, 0, 0};      // producer empty-phase per stage (tid 0)
    int fills = 0;                    // total fills issued (tid 0)
    int cons  = 0;                    // total consumes (gates threads)

    for (int s = 0; s < S_; s++) {
        // Prefetch pointwise tail scalars (overlaps gates)
        if (tid >= 16 && tid < 25) {
            int t9 = tid - 16;
            float v;
            if (t9 == 0)      v = tau[bid * S_ + s];
            else if (t9 < 5)  v = Amat[t9 - 1];
            else if (t9 < 7)  v = Wab[t9 - 5];
            else              v = Wxb[t9 - 7];
            sPre[t9] = v;
        }

        // ============== Phase 1: gates GEMM (threads 0..255) ==============
        if (tid < 256) {
            if (tid == 0) {
#pragma unroll
                for (int i = 0; i < NSTAGE; i++) {
                    int st = fills % NSTAGE;
                    if (fills >= NSTAGE) { MBAR_WAIT(mb_empty[st], eph[st]); eph[st] ^= 1; }
                    int kb = fills % NKH;
                    MBEXPECT(mb_full[st], XBLK_BYTES);
                    bulk_g2s(xstage + st * XBLK_BYTES,
                             (const char*)g_X + (size_t)(kstart + kb) * XBLK_BYTES,
                             XBLK_BYTES, mb_full[st]);
                    fills++;
                }
            }

            float acc[2][4][4];
#pragma unroll
            for (int mi = 0; mi < 2; mi++)
#pragma unroll
                for (int ni = 0; ni < 4; ni++)
#pragma unroll
                    for (int e = 0; e < 4; e++) acc[mi][ni][e] = 0.0f;

            for (int kb = 0; kb < NKH; kb++) {
                int st = cons % NSTAGE;
                uint32_t sx = xstage + st * XBLK_BYTES;
                uint32_t sw = wres + kb * WBLK_BYTES;

                MBAR_WAIT(mb_full[st], fph[st]); fph[st] ^= 1;

                uint32_t a[2][2][4], bw[2][4][2];
#pragma unroll
                for (int ks = 0; ks < 2; ks++) {
                    const uint32_t ko = ks * 32;
                    LDSM_X4(a[ks][0][0], a[ks][0][1], a[ks][0][2], a[ks][0][3], sx + a_off0 + ko);
                    LDSM_X4(a[ks][1][0], a[ks][1][1], a[ks][1][2], a[ks][1][3], sx + a_off1 + ko);
                    LDSM_X4(bw[ks][0][0], bw[ks][0][1], bw[ks][1][0], bw[ks][1][1], sw + b_off0 + ko);
                    LDSM_X4(bw[ks][2][0], bw[ks][2][1], bw[ks][3][0], bw[ks][3][1], sw + b_off1 + ko);
                }
#pragma unroll
                for (int ks = 0; ks < 2; ks++)
#pragma unroll
                    for (int mi = 0; mi < 2; mi++)
#pragma unroll
                        for (int ni = 0; ni < 4; ni++)
                            MMA_F16(acc[mi][ni], a[ks][mi], bw[ks][ni]);

                MBARRIVE(mb_empty[st]);
                cons++;

                if (tid == 0 && kb + NSTAGE < NKH) {
                    int stf = fills % NSTAGE;
                    MBAR_WAIT(mb_empty[stf], eph[stf]); eph[stf] ^= 1;
                    int kbf = fills % NKH;
                    MBEXPECT(mb_full[stf], XBLK_BYTES);
                    bulk_g2s(xstage + stf * XBLK_BYTES,
                             (const char*)g_X + (size_t)(kstart + kbf) * XBLK_BYTES,
                             XBLK_BYTES, mb_full[stf]);
                    fills++;
                }
            }

            float* gout = g_gates[ki];
            const int n0 = nt * 64 + ng * 32;
#pragma unroll
            for (int mi = 0; mi < 2; mi++) {
                int r0 = mp * 32 + mi * 16 + lr;
#pragma unroll
                for (int ni = 0; ni < 4; ni++) {
                    int col = n0 + ni * 8 + lc * 2;
                    gout[(size_t)r0 * NG + col]           = acc[mi][ni][0];
                    gout[(size_t)r0 * NG + col + 1]       = acc[mi][ni][1];
                    gout[(size_t)(r0 + 8) * NG + col]     = acc[mi][ni][2];
                    gout[(size_t)(r0 + 8) * NG + col + 1] = acc[mi][ni][3];
                }
            }
        }

        // ============== Grid barrier: gates -> pointwise ==============
        __syncthreads();
        if (tid == 0) {
            __threadfence();
            unsigned gen = *(volatile unsigned*)&g_bar_gen;
            if (atomicAdd(&g_bar_count, 1u) == (unsigned)(gridDim.x - 1)) {
                g_bar_count = 0;
                __threadfence();
                atomicAdd(&g_bar_gen, 1u);
            } else {
                while (*(volatile unsigned*)&g_bar_gen == gen) {}
            }
            __threadfence();
        }
        __syncthreads();

        // ============== Phase 2: pointwise (all 512, b = bid) ==============
        {
            const int b = bid;
            const float x0 = g_xstate[b * 2 + 0];
            const float x1 = g_xstate[b * 2 + 1];

            const float4* gb0 = (const float4*)(g_gates[0] + (size_t)b * NG);
            const float4* gb1 = (const float4*)(g_gates[1] + (size_t)b * NG);
            float* outz = out + ((size_t)b * S_ + s) * ZW;

            float wa0 = 0.f, wa1 = 0.f, wx0 = 0.f, wx1 = 0.f;
#pragma unroll
            for (int j = 0; j < 2; j++) {
                const int n = tid + j * 512;
                float4 p0 = gb0[n];
                float4 p1 = gb1[n];
                float4 bi = g_bias4[n];
                float4 xa = g_wx2a[n];
                float4 xb = g_wx2b[n];
                float i_ = p0.x + p1.x + bi.x + x0 * xa.x + x1 * xb.x;
                float f_ = p0.y + p1.y + bi.y + x0 * xa.y + x1 * xb.y;
                float g_ = p0.z + p1.z + bi.z + x0 * xa.z + x1 * xb.z;
                float o_ = p0.w + p1.w + bi.w + x0 * xa.w + x1 * xb.w;
                float c  = g_cstate[b * H_ + n];
                float cn = sigf(f_) * c + sigf(i_) * tanhfast(g_);
                float hn = sigf(o_) * tanhfast(cn);
                g_cstate[b * H_ + n] = cn;
                store_x(b, IN_ + n, hn);
                outz[SD_ + n] = hn;
                float4 ww = g_wawx4[n];
                wa0 += ww.x * hn;
                wa1 += ww.y * hn;
                wx0 += ww.z * hn;
                wx1 += ww.w * hn;
            }

            unsigned mask = 0xffffffffu;
#pragma unroll
            for (int off = 16; off > 0; off >>= 1) {
                wa0 += __shfl_down_sync(mask, wa0, off);
                wa1 += __shfl_down_sync(mask, wa1, off);
                wx0 += __shfl_down_sync(mask, wx0, off);
                wx1 += __shfl_down_sync(mask, wx1, off);
            }
            if (lane == 0) {
                red[wid][0] = wa0; red[wid][1] = wa1;
                red[wid][2] = wx0; red[wid][3] = wx1;
            }
            __syncthreads();

            if (wid == 0) {
                float s0 = 0.f, s1 = 0.f, s2 = 0.f, s3 = 0.f;
                if (lane < 16) {
                    s0 = red[lane][0]; s1 = red[lane][1];
                    s2 = red[lane][2]; s3 = red[lane][3];
                }
#pragma unroll
                for (int off = 8; off > 0; off >>= 1) {
                    s0 += __shfl_down_sync(mask, s0, off);
                    s1 += __shfl_down_sync(mask, s1, off);
                    s2 += __shfl_down_sync(mask, s2, off);
                    s3 += __shfl_down_sync(mask, s3, off);
                }
                if (lane == 0) {
                    float t   = sPre[0];
                    float xm0 = x0 + t * (sPre[1] * x0 + sPre[2] * x1);
                    float xm1 = x1 + t * (sPre[3] * x0 + sPre[4] * x1);
                    float a0  = sigf(s0 + sPre[5]);
                    float a1  = sigf(s1 + sPre[6]);
                    float xt0 = s2 + sPre[7];
                    float xt1 = s3 + sPre[8];
                    float xn0 = a0 * xm0 + (1.0f - a0) * xt0;
                    float xn1 = a1 * xm1 + (1.0f - a1) * xt1;
                    g_xstate[b * 2 + 0] = xn0;
                    g_xstate[b * 2 + 1] = xn1;
                    outz[0] = xn0;
                    outz[1] = xn1;
                    float* cf = out + OUT_COEF + ((size_t)b * S_ + s) * SD_;
                    cf[0] = a0;
                    cf[1] = a1;
                }
            }

            if (s + 1 < S_ && tid >= 128 && tid < 128 + IN_) {
                int u = tid - 128;
                store_x(b, u, rnn_input[((size_t)b * S_ + (s + 1)) * IN_ + u]);
            }
        }

        // ============== Grid barrier: pointwise -> next gates ==============
        __syncthreads();
        if (tid == 0) {
            __threadfence();
            unsigned gen = *(volatile unsigned*)&g_bar_gen;
            if (atomicAdd(&g_bar_count, 1u) == (unsigned)(gridDim.x - 1)) {
                g_bar_count = 0;
                __threadfence();
                atomicAdd(&g_bar_gen, 1u);
            } else {
                while (*(volatile unsigned*)&g_bar_gen == gen) {}
            }
            __threadfence();
        }
        __syncthreads();
    }
}

// ---------------------------------------------------------------------------
// Final: z_f = outputs[:, -1, :], c_z_f = [c0[:, :2], c_final]
// ---------------------------------------------------------------------------
__global__ void final_out(const float* __restrict__ c0, float* __restrict__ out) {
    int b = blockIdx.x;
    float* zf  = out + OUT_ZF  + (size_t)b * ZW;
    float* czf = out + OUT_CZF + (size_t)b * ZW;
    const float* last = out + ((size_t)b * S_ + (S_ - 1)) * ZW;
    for (int k = threadIdx.x; k < ZW; k += 256) {
        zf[k] = last[k];
        czf[k] = (k < SD_) ? c0[b * ZW + k] : g_cstate[b * H_ + (k - SD_)];
    }
}

// ---------------------------------------------------------------------------
extern "C" void kernel_launch(void* const* d_in, const int* in_sizes, int n_in,
                              void* d_out, int out_size) {
    const float* rnn_input = (const float*)d_in[0];
    const float* z0        = (const float*)d_in[1];
    const float* c0        = (const float*)d_in[2];
    const float* tau       = (const float*)d_in[3];
    const float* A         = (const float*)d_in[4];
    const float* WU_w      = (const float*)d_in[5];
    const float* WU_b      = (const float*)d_in[6];
    const float* Wa_w      = (const float*)d_in[7];
    const float* Wa_b      = (const float*)d_in[8];
    const float* Wx_w      = (const float*)d_in[9];
    const float* Wx_b      = (const float*)d_in[10];
    float* out = (float*)d_out;

    cudaFuncSetAttribute(persistent_scan, cudaFuncAttributeMaxDynamicSharedMemorySize, SMEM_DYN);

    prep_w<<<dim3(64, NKB), 256>>>(WU_w);
    prep_small<<<4, 256>>>(WU_w, WU_b, Wa_w, Wx_w);
    init_pack<<<B_, 128>>>(z0, c0, rnn_input);
    persistent_scan<<<128, 512, SMEM_DYN>>>(out, Wa_b, Wx_b, A, tau, rnn_input);
    final_out<<<B_, 256>>>(c0, out);
}

// round 17
// speedup vs baseline: 1.4791x; 1.4791x over previous
#include <cuda_runtime.h>
#include <cuda_fp16.h>
#include <cstdint>
#include <cstddef>

// ---------------------------------------------------------------------------
// Problem constants
// ---------------------------------------------------------------------------
#define B_   128
#define S_   256
#define H_   1024
#define IN_  64
#define SD_  2
#define KGEMM 1088           // u(64) + h(1024); x handled as rank-2 fp32 update
#define NKB  34              // K blocks of 32
#define NKH  17              // K blocks per K-split half
#define ZW   (SD_ + H_)      // 1026
#define NG   4096

#define OUT_ZF   ((size_t)B_ * S_ * ZW)
#define OUT_CZF  (OUT_ZF + (size_t)B_ * ZW)
#define OUT_COEF (OUT_CZF + (size_t)B_ * ZW)

// Blocked layouts: rows padded to 40 fp16 (80 B) for conflict-free LDSM
#define ROWB 40
#define XBLK_BYTES  (128 * ROWB * 2)          // 10240 per K-block
#define WBLK_BYTES  (64 * ROWB * 2)           // 5120 per (ntile64, kb)
#define STAGE_BYTES (XBLK_BYTES + WBLK_BYTES) // 15360
#define NSTAGE 4
#define SMEM_DYN    (128 + NSTAGE * STAGE_BYTES)        // 61568

// ---------------------------------------------------------------------------
// Device-global scratch
// ---------------------------------------------------------------------------
__device__ __align__(128) __half g_X[(size_t)NKB * 128 * ROWB];      // fp16 X image
__device__ __align__(128) __half g_W[(size_t)64 * NKB * 64 * ROWB];  // fp16 W image
__device__ float g_gates[2][(size_t)B_ * NG];   // two K-split partials (unit-major)
__device__ float4 g_bias4[H_];                  // per-unit (i,f,g,o) bias
__device__ float4 g_wawx4[H_];                  // {Wa0, Wa1, Wx0, Wx1} per unit
__device__ float4 g_wx2a[H_];                   // W[:,0] per unit (i,f,g,o)
__device__ float4 g_wx2b[H_];                   // W[:,1] per unit (i,f,g,o)
__device__ float g_cstate[B_ * H_];
__device__ float g_xstate[B_ * 2];

// ---------------------------------------------------------------------------
// Helpers
// ---------------------------------------------------------------------------
__device__ __forceinline__ float sigf(float x) { return 1.0f / (1.0f + __expf(-x)); }
__device__ __forceinline__ float tanhfast(float x) { return 2.0f / (1.0f + __expf(-2.0f * x)) - 1.0f; }

// Streaming store (evict-first): keeps the big output stream from evicting W in L2
__device__ __forceinline__ void stcs(float* p, float v) {
    asm volatile("st.global.cs.f32 [%0], %1;" :: "l"(p), "f"(v) : "memory");
}

// X image column mapping: k 0..63 = u_t, k 64..1087 = h
__device__ __forceinline__ void store_x(int m, int k, float v) {
    int kb = k >> 5, kk = k & 31;
    g_X[((size_t)kb * 128 + m) * ROWB + kk] = __float2half_rn(v);
}

__device__ __forceinline__ uint32_t smem_u32(const void* p) {
    uint32_t a;
    asm("{ .reg .u64 t; cvta.to.shared.u64 t, %1; cvt.u32.u64 %0, t; }" : "=r"(a) : "l"(p));
    return a;
}

#define MBINIT(a, c)  asm volatile("mbarrier.init.shared.b64 [%0], %1;" :: "r"(a), "r"(c) : "memory")
#define MBEXPECT(a,b) asm volatile("mbarrier.arrive.expect_tx.shared.b64 _, [%0], %1;" :: "r"(a), "r"(b) : "memory")
#define MBARRIVE(a)   asm volatile("mbarrier.arrive.shared.b64 _, [%0];" :: "r"(a) : "memory")

#define MBAR_WAIT(mbar, ph) do {                                             \
    uint32_t _m = (mbar); uint32_t _p = (ph); uint32_t _ok;                  \
    asm volatile("{\n\t.reg .pred p;\n\t"                                    \
        "mbarrier.try_wait.parity.acquire.cta.shared::cta.b64 p, [%1], %2;\n\t" \
        "selp.b32 %0, 1, 0, p;\n\t}" : "=r"(_ok) : "r"(_m), "r"(_p) : "memory"); \
    while (!_ok) {                                                           \
        asm volatile("{\n\t.reg .pred p;\n\t"                                \
            "mbarrier.try_wait.parity.acquire.cta.shared::cta.b64 p, [%1], %2, 0x989680;\n\t" \
            "selp.b32 %0, 1, 0, p;\n\t}" : "=r"(_ok) : "r"(_m), "r"(_p) : "memory"); \
    }                                                                        \
} while (0)

__device__ __forceinline__ void bulk_g2s(uint32_t dst, const void* src, uint32_t bytes, uint32_t mbar) {
    asm volatile("cp.async.bulk.shared::cluster.global.mbarrier::complete_tx::bytes [%0], [%1], %2, [%3];"
                 :: "r"(dst), "l"(src), "r"(bytes), "r"(mbar) : "memory");
}

#define MMA_F16(acc, a, b)                                                   \
    asm volatile("mma.sync.aligned.m16n8k16.row.col.f32.f16.f16.f32 "       \
                 "{%0,%1,%2,%3},{%4,%5,%6,%7},{%8,%9},{%0,%1,%2,%3};"        \
                 : "+f"((acc)[0]), "+f"((acc)[1]), "+f"((acc)[2]), "+f"((acc)[3]) \
                 : "r"((a)[0]), "r"((a)[1]), "r"((a)[2]), "r"((a)[3]),       \
                   "r"((b)[0]), "r"((b)[1]))

#define LDSM_X4(r0, r1, r2, r3, addr)                                        \
    asm volatile("ldmatrix.sync.aligned.m8n8.x4.shared.b16 {%0,%1,%2,%3}, [%4];" \
                 : "=r"(r0), "=r"(r1), "=r"(r2), "=r"(r3) : "r"(addr))

// Unit-major permutation: GEMM column j -> W row (j&3)*H + (j>>2)
__device__ __forceinline__ int orig_row(int j) {
    return (j & 3) * H_ + (j >> 2);
}

// ---------------------------------------------------------------------------
// prep_w: W [4096][1090] fp32 -> blocked, unit-major, fp16 image
// ---------------------------------------------------------------------------
__global__ void prep_w(const float* __restrict__ W) {
    int nt = blockIdx.x, kb = blockIdx.y;
    size_t base = ((size_t)(nt * NKB + kb)) * 64 * ROWB;
    for (int i = threadIdx.x; i < 64 * ROWB; i += 256) {
        int nloc = i / ROWB, kk = i % ROWB;
        int j = nt * 64 + nloc;
        int n = orig_row(j);
        int k = kb * 32 + kk;          // GEMM k; original col = k + SD_
        float v = (kk < 32 && k < KGEMM) ? W[(size_t)n * (SD_ + IN_ + H_) + (k + SD_)] : 0.0f;
        g_W[base + i] = __float2half_rn(v);
    }
}

// ---------------------------------------------------------------------------
// prep_small: pack bias / Wa / Wx / W x-columns as per-unit float4 (fp32 exact)
// ---------------------------------------------------------------------------
__global__ void prep_small(const float* __restrict__ W, const float* __restrict__ WUb,
                           const float* __restrict__ Wa, const float* __restrict__ Wx) {
    int u = blockIdx.x * 256 + threadIdx.x;
    if (u >= H_) return;
    const int KW = SD_ + IN_ + H_;
    g_bias4[u] = make_float4(WUb[u], WUb[H_ + u], WUb[2 * H_ + u], WUb[3 * H_ + u]);
    g_wawx4[u] = make_float4(Wa[u], Wa[H_ + u], Wx[u], Wx[H_ + u]);
    g_wx2a[u] = make_float4(W[(size_t)u * KW], W[(size_t)(H_ + u) * KW],
                            W[(size_t)(2 * H_ + u) * KW], W[(size_t)(3 * H_ + u) * KW]);
    g_wx2b[u] = make_float4(W[(size_t)u * KW + 1], W[(size_t)(H_ + u) * KW + 1],
                            W[(size_t)(2 * H_ + u) * KW + 1], W[(size_t)(3 * H_ + u) * KW + 1]);
}

// ---------------------------------------------------------------------------
// init_pack: X image for step 0 ([u_0 | h_0]), states
// ---------------------------------------------------------------------------
__global__ void init_pack(const float* __restrict__ z0, const float* __restrict__ c0,
                          const float* __restrict__ rnn_input) {
    int b = blockIdx.x;
    for (int i = threadIdx.x; i < NKB * ROWB; i += 128) {
        int kb = i / ROWB, kk = i % ROWB;
        int k = kb * 32 + kk;
        float v = 0.0f;
        if (kk < 32) {
            if (k < IN_)            v = rnn_input[((size_t)b * S_) * IN_ + k];
            else if (k < KGEMM)     v = z0[b * ZW + SD_ + (k - IN_)];
        }
        g_X[((size_t)kb * 128 + b) * ROWB + kk] = __float2half_rn(v);
    }
    for (int n = threadIdx.x; n < H_; n += 128)
        g_cstate[b * H_ + n] = c0[b * ZW + SD_ + n];
    if (threadIdx.x < 2) g_xstate[b * 2 + threadIdx.x] = z0[b * ZW + threadIdx.x];
}

// ---------------------------------------------------------------------------
// Fill one pipeline stage (producer thread 0)
// ---------------------------------------------------------------------------
__device__ __forceinline__ void fill_stage(uint32_t tiles_u, int stage, int nt, int kg,
                                           uint32_t mbar) {
    uint32_t sb = tiles_u + (uint32_t)stage * STAGE_BYTES;
    MBEXPECT(mbar, STAGE_BYTES);
    bulk_g2s(sb, (const char*)g_X + (size_t)kg * XBLK_BYTES, XBLK_BYTES, mbar);
    size_t woff = (size_t)(nt * NKB + kg) * WBLK_BYTES;
    bulk_g2s(sb + XBLK_BYTES, (const char*)g_W + woff, WBLK_BYTES, mbar);
}

// ---------------------------------------------------------------------------
// gates_hmma: partial C = Xfp16 @ Wfp16^T over one K half (1-term fp16)
// grid = (64 ntiles, 2 ksplit), 256 threads = 8 warps (2/SMSP), 1 CTA/SM.
// 4-stage cp.async.bulk pipeline. All 8 LDSM issued before the 16 MMAs.
// ---------------------------------------------------------------------------
__global__ void __launch_bounds__(256, 1)
gates_hmma() {
    extern __shared__ char dsm[];
    uint32_t ub = smem_u32(dsm);
    const int nt  = blockIdx.x;
    const int ki  = blockIdx.y;          // K-split half
    const int kstart = ki * NKH;
    const int tid = threadIdx.x;
    const int wid = tid >> 5;
    const int lane = tid & 31;
    const int lr = lane >> 2, lc = lane & 3;
    const int mp = wid & 3;              // M position (32 rows)
    const int ng = wid >> 2;             // N group (32 cols)

    uint32_t mb_full[NSTAGE], mb_empty[NSTAGE];
#pragma unroll
    for (int s = 0; s < NSTAGE; s++) {
        mb_full[s]  = ub + s * 8;
        mb_empty[s] = ub + 32 + s * 8;
    }
    const uint32_t tiles_u = ub + 128;

    // ldmatrix per-lane byte offsets (within a tile image)
    const int a_row = mp * 32 + (lane & 7) + ((lane >> 3) & 1) * 8;
    const uint32_t a_off0 = (uint32_t)(a_row * 80 + (lane >> 4) * 16);           // mi=0
    const uint32_t a_off1 = a_off0 + 16 * 80;                                    // mi=1
    const int b_row0 = ng * 32 + (lane >> 4) * 8 + (lane & 7);                   // g=0
    const uint32_t b_off0 = (uint32_t)(b_row0 * 80 + ((lane >> 3) & 1) * 16);
    const uint32_t b_off1 = b_off0 + 16 * 80;                                    // g=1

    if (tid == 0) {
#pragma unroll
        for (int s = 0; s < NSTAGE; s++) {
            MBINIT(mb_full[s], 1);
            MBINIT(mb_empty[s], 256);
        }
        asm volatile("fence.proxy.async.shared::cta;" ::: "memory");
    }
    __syncthreads();

    // Prologue: fill stages 0..2 (3 K-blocks in flight)
    if (tid == 0) {
#pragma unroll
        for (int kb = 0; kb < 3; kb++)
            fill_stage(tiles_u, kb, nt, kstart + kb, mb_full[kb]);
    }

    float acc[2][4][4];
#pragma unroll
    for (int mi = 0; mi < 2; mi++)
#pragma unroll
        for (int ni = 0; ni < 4; ni++)
#pragma unroll
            for (int e = 0; e < 4; e++) acc[mi][ni][e] = 0.0f;

    int fph[NSTAGE] = {0, 0, 0, 0}, eph[NSTAGE] = {0, 0, 0, 0};

    for (int kb = 0; kb < NKH; kb++) {
        int st = kb & (NSTAGE - 1);
        uint32_t sx = tiles_u + st * STAGE_BYTES;
        uint32_t sw = sx + XBLK_BYTES;

        MBAR_WAIT(mb_full[st], fph[st]); fph[st] ^= 1;

        // Load ALL fragments for both ks halves (8 LDSM), then 16 MMAs.
        uint32_t a[2][2][4], bw[2][4][2];
#pragma unroll
        for (int ks = 0; ks < 2; ks++) {
            const uint32_t ko = ks * 32;
            LDSM_X4(a[ks][0][0], a[ks][0][1], a[ks][0][2], a[ks][0][3], sx + a_off0 + ko);
            LDSM_X4(a[ks][1][0], a[ks][1][1], a[ks][1][2], a[ks][1][3], sx + a_off1 + ko);
            LDSM_X4(bw[ks][0][0], bw[ks][0][1], bw[ks][1][0], bw[ks][1][1], sw + b_off0 + ko);
            LDSM_X4(bw[ks][2][0], bw[ks][2][1], bw[ks][3][0], bw[ks][3][1], sw + b_off1 + ko);
        }
#pragma unroll
        for (int ks = 0; ks < 2; ks++)
#pragma unroll
            for (int mi = 0; mi < 2; mi++)
#pragma unroll
                for (int ni = 0; ni < 4; ni++)
                    MMA_F16(acc[mi][ni], a[ks][mi], bw[ks][ni]);

        MBARRIVE(mb_empty[st]);

        if (tid == 0 && kb + 3 < NKH) {
            int stn = (kb + 3) & (NSTAGE - 1);
            if (kb >= 1) {  // stage 3's first fill (kb==0) needs no empty-wait
                MBAR_WAIT(mb_empty[stn], eph[stn]); eph[stn] ^= 1;
            }
            fill_stage(tiles_u, stn, nt, kstart + kb + 3, mb_full[stn]);
        }
    }

    // Store partial accumulators
    float* gout = g_gates[ki];
    const int n0 = nt * 64 + ng * 32;
#pragma unroll
    for (int mi = 0; mi < 2; mi++) {
        int r0 = mp * 32 + mi * 16 + lr;
#pragma unroll
        for (int ni = 0; ni < 4; ni++) {
            int col = n0 + ni * 8 + lc * 2;
            gout[(size_t)r0 * NG + col]           = acc[mi][ni][0];
            gout[(size_t)r0 * NG + col + 1]       = acc[mi][ni][1];
            gout[(size_t)(r0 + 8) * NG + col]     = acc[mi][ni][2];
            gout[(size_t)(r0 + 8) * NG + col + 1] = acc[mi][ni][3];
        }
    }
}

// ---------------------------------------------------------------------------
// Pointwise step: float4 unit-major gate reads + rank-2 x contribution +
// prefetched tail scalars. Output writes use st.global.cs (evict-first) so
// the 134 MB output stream doesn't evict the W image from L2.
// grid = B_, 1024 threads.
// ---------------------------------------------------------------------------
__global__ void __launch_bounds__(1024, 1)
step_pointwise(const float* __restrict__ Wab, const float* __restrict__ Wxb,
               const float* __restrict__ Amat, const float* __restrict__ tau,
               const float* __restrict__ rnn_input,
               float* __restrict__ out, int s) {
    const int b = blockIdx.x;
    const int tid = threadIdx.x;
    const int lane = tid & 31;
    const int wid = tid >> 5;

    __shared__ float sPre[12];
    if (tid < 9) {
        float v;
        if (tid == 0)      v = tau[b * S_ + s];
        else if (tid < 5)  v = Amat[tid - 1];
        else if (tid < 7)  v = Wab[tid - 5];
        else               v = Wxb[tid - 7];
        sPre[tid] = v;
    }

    const float x0 = g_xstate[b * 2 + 0];
    const float x1 = g_xstate[b * 2 + 1];

    const float4* gb0 = (const float4*)(g_gates[0] + (size_t)b * NG);
    const float4* gb1 = (const float4*)(g_gates[1] + (size_t)b * NG);
    float* outz = out + ((size_t)b * S_ + s) * ZW;

    const int n = tid;  // unit index 0..1023
    float4 p0 = gb0[n];
    float4 p1 = gb1[n];
    float4 bi = g_bias4[n];
    float4 xa = g_wx2a[n];
    float4 xb = g_wx2b[n];
    float i_ = p0.x + p1.x + bi.x + x0 * xa.x + x1 * xb.x;
    float f_ = p0.y + p1.y + bi.y + x0 * xa.y + x1 * xb.y;
    float g_ = p0.z + p1.z + bi.z + x0 * xa.z + x1 * xb.z;
    float o_ = p0.w + p1.w + bi.w + x0 * xa.w + x1 * xb.w;
    float c  = g_cstate[b * H_ + n];
    float cn = sigf(f_) * c + sigf(i_) * tanhfast(g_);
    float hn = sigf(o_) * tanhfast(cn);
    g_cstate[b * H_ + n] = cn;
    store_x(b, IN_ + n, hn);
    stcs(&outz[SD_ + n], hn);

    float4 ww = g_wawx4[n];
    float wa0 = ww.x * hn;
    float wa1 = ww.y * hn;
    float wx0 = ww.z * hn;
    float wx1 = ww.w * hn;

    __shared__ float red[32][4];
    unsigned mask = 0xffffffffu;
#pragma unroll
    for (int off = 16; off > 0; off >>= 1) {
        wa0 += __shfl_down_sync(mask, wa0, off);
        wa1 += __shfl_down_sync(mask, wa1, off);
        wx0 += __shfl_down_sync(mask, wx0, off);
        wx1 += __shfl_down_sync(mask, wx1, off);
    }
    if (lane == 0) {
        red[wid][0] = wa0; red[wid][1] = wa1;
        red[wid][2] = wx0; red[wid][3] = wx1;
    }
    __syncthreads();

    if (wid == 0) {
        float s0 = red[lane][0], s1 = red[lane][1];
        float s2 = red[lane][2], s3 = red[lane][3];
#pragma unroll
        for (int off = 16; off > 0; off >>= 1) {
            s0 += __shfl_down_sync(mask, s0, off);
            s1 += __shfl_down_sync(mask, s1, off);
            s2 += __shfl_down_sync(mask, s2, off);
            s3 += __shfl_down_sync(mask, s3, off);
        }
        if (lane == 0) {
            float t   = sPre[0];
            float xm0 = x0 + t * (sPre[1] * x0 + sPre[2] * x1);
            float xm1 = x1 + t * (sPre[3] * x0 + sPre[4] * x1);
            float a0  = sigf(s0 + sPre[5]);
            float a1  = sigf(s1 + sPre[6]);
            float xt0 = s2 + sPre[7];
            float xt1 = s3 + sPre[8];
            float xn0 = a0 * xm0 + (1.0f - a0) * xt0;
            float xn1 = a1 * xm1 + (1.0f - a1) * xt1;
            g_xstate[b * 2 + 0] = xn0;
            g_xstate[b * 2 + 1] = xn1;
            stcs(&outz[0], xn0);
            stcs(&outz[1], xn1);
            float* cf = out + OUT_COEF + ((size_t)b * S_ + s) * SD_;
            stcs(&cf[0], a0);
            stcs(&cf[1], a1);
        }
    }

    if (s + 1 < S_ && tid >= 128 && tid < 128 + IN_) {
        int u = tid - 128;
        store_x(b, u, rnn_input[((size_t)b * S_ + (s + 1)) * IN_ + u]);
    }
}

// ---------------------------------------------------------------------------
// Final: z_f = outputs[:, -1, :], c_z_f = [c0[:, :2], c_final]
// ---------------------------------------------------------------------------
__global__ void final_out(const float* __restrict__ c0, float* __restrict__ out) {
    int b = blockIdx.x;
    float* zf  = out + OUT_ZF  + (size_t)b * ZW;
    float* czf = out + OUT_CZF + (size_t)b * ZW;
    const float* last = out + ((size_t)b * S_ + (S_ - 1)) * ZW;
    for (int k = threadIdx.x; k < ZW; k += 256) {
        zf[k] = last[k];
        czf[k] = (k < SD_) ? c0[b * ZW + k] : g_cstate[b * H_ + (k - SD_)];
    }
}

// ---------------------------------------------------------------------------
extern "C" void kernel_launch(void* const* d_in, const int* in_sizes, int n_in,
                              void* d_out, int out_size) {
    const float* rnn_input = (const float*)d_in[0];
    const float* z0        = (const float*)d_in[1];
    const float* c0        = (const float*)d_in[2];
    const float* tau       = (const float*)d_in[3];
    const float* A         = (const float*)d_in[4];
    const float* WU_w      = (const float*)d_in[5];
    const float* WU_b      = (const float*)d_in[6];
    const float* Wa_w      = (const float*)d_in[7];
    const float* Wa_b      = (const float*)d_in[8];
    const float* Wx_w      = (const float*)d_in[9];
    const float* Wx_b      = (const float*)d_in[10];
    float* out = (float*)d_out;

    cudaFuncSetAttribute(gates_hmma, cudaFuncAttributeMaxDynamicSharedMemorySize, SMEM_DYN);

    prep_w<<<dim3(64, NKB), 256>>>(WU_w);
    prep_small<<<4, 256>>>(WU_w, WU_b, Wa_w, Wx_w);
    init_pack<<<B_, 128>>>(z0, c0, rnn_input);
    for (int s = 0; s < S_; s++) {
        gates_hmma<<<dim3(64, 2), 256, SMEM_DYN>>>();
        step_pointwise<<<B_, 1024>>>(Wa_b, Wx_b, A, tau, rnn_input, out, s);
    }
    final_out<<<B_, 256>>>(c0, out);
}